// round 1
// baseline (speedup 1.0000x reference)
#include <cuda_runtime.h>

#define NN   50000
#define EE   600000
#define DD   128
#define DOUT 64

// ---------------- scratch (no allocation allowed) ----------------
__device__ float g_bufA[(size_t)NN * DD];
__device__ float g_bufB[(size_t)NN * DD];
__device__ int   g_deg[NN];
__device__ int   g_cnt[NN];
__device__ int   g_off[NN + 1];
__device__ int   g_csr[EE];
__device__ int   g_is64;

// ---------------- edge_index dtype sniffing ----------------
// If edge_index is int64 (values < 50000, nonneg), every odd 32-bit word of
// the first 64 elements is 0. If int32, those words are random src indices.
__global__ void detect_kernel(const unsigned int* __restrict__ w) {
    int is64 = 1;
    for (int i = 1; i < 128; i += 2)
        if (w[i] != 0u) { is64 = 0; break; }
    g_is64 = is64;
}

__device__ __forceinline__ int edge_idx(const void* ei, int which, int e) {
    if (g_is64) {
        const long long* p = (const long long*)ei;
        return (int)p[(size_t)which * EE + e];
    } else {
        const int* p = (const int*)ei;
        return p[which * EE + e];
    }
}

// ---------------- CSR build ----------------
__global__ void zero_kernel() {
    int i = blockIdx.x * blockDim.x + threadIdx.x;
    if (i < NN) { g_deg[i] = 0; g_cnt[i] = 0; }
}

__global__ void hist_kernel(const void* ei) {
    int e = blockIdx.x * blockDim.x + threadIdx.x;
    if (e < EE) atomicAdd(&g_deg[edge_idx(ei, 1, e)], 1);
}

__global__ void scan_kernel() {
    __shared__ int part[1024];
    int t = threadIdx.x;
    const int chunk = (NN + 1023) / 1024;       // 49
    int lo = t * chunk;
    int hi = min(lo + chunk, NN);
    int s = 0;
    for (int i = lo; i < hi; i++) s += g_deg[i];
    part[t] = s;
    __syncthreads();
    // Hillis-Steele inclusive scan over 1024 partials
    for (int d = 1; d < 1024; d <<= 1) {
        int v = (t >= d) ? part[t - d] : 0;
        __syncthreads();
        part[t] += v;
        __syncthreads();
    }
    int run = (t == 0) ? 0 : part[t - 1];
    for (int i = lo; i < hi; i++) { g_off[i] = run; run += g_deg[i]; }
    if (t == 1023) g_off[NN] = part[1023];
}

__global__ void fill_kernel(const void* ei) {
    int e = blockIdx.x * blockDim.x + threadIdx.x;
    if (e < EE) {
        int d = edge_idx(ei, 1, e);
        int s = edge_idx(ei, 0, e);
        int pos = g_off[d] + atomicAdd(&g_cnt[d], 1);
        g_csr[pos] = s;
    }
}

// ---------------- GEMM: C[N,BN] = (reluIn? relu(A) : A)[N,128] @ W[128,BN] + bias ----------------
// BM=64, BK=16, 256 threads, micro-tile TM=4 x TN (8 for BN=128, 4 for BN=64)
template <int BN, int TN>
__global__ void __launch_bounds__(256) gemm_kernel(
    const float* __restrict__ A, const float* __restrict__ W,
    const float* __restrict__ bias, float* __restrict__ C, int reluIn)
{
    const int BM = 64, BK = 16, TM = 4;
    __shared__ float As[BK][BM];
    __shared__ float Bs[BK][BN];

    int tid = threadIdx.x;
    int tx = tid & 15;     // 0..15 -> output column group
    int ty = tid >> 4;     // 0..15 -> output row group
    int row0 = blockIdx.x * BM;

    float acc[TM][TN];
#pragma unroll
    for (int i = 0; i < TM; i++)
#pragma unroll
        for (int j = 0; j < TN; j++) acc[i][j] = 0.f;

    int arow = tid >> 2;   // 0..63
    int ac4  = tid & 3;    // 0..3 (which k-subchunk of 4)
    int grow = row0 + arow;

    for (int k0 = 0; k0 < DD; k0 += BK) {
        // stage A (transposed) with fused input relu + row guard
        float4 av = make_float4(0.f, 0.f, 0.f, 0.f);
        if (grow < NN)
            av = *(const float4*)&A[(size_t)grow * DD + k0 + ac4 * 4];
        if (reluIn) {
            av.x = fmaxf(av.x, 0.f); av.y = fmaxf(av.y, 0.f);
            av.z = fmaxf(av.z, 0.f); av.w = fmaxf(av.w, 0.f);
        }
        As[ac4 * 4 + 0][arow] = av.x;
        As[ac4 * 4 + 1][arow] = av.y;
        As[ac4 * 4 + 2][arow] = av.z;
        As[ac4 * 4 + 3][arow] = av.w;

        // stage W tile: rows k0..k0+15, all BN columns -> contiguous chunk
        {
            const float4* wsrc = (const float4*)(W + (size_t)k0 * BN);
            float4* bdst = (float4*)&Bs[0][0];
#pragma unroll
            for (int i = 0; i < (BK * BN / 4) / 256; i++)
                bdst[tid + i * 256] = wsrc[tid + i * 256];
        }
        __syncthreads();

#pragma unroll
        for (int k = 0; k < BK; k++) {
            float4 a4 = *(const float4*)&As[k][ty * TM];
            float aa[TM] = {a4.x, a4.y, a4.z, a4.w};
            float b[TN];
#pragma unroll
            for (int j = 0; j < TN; j += 4) {
                float4 bv = *(const float4*)&Bs[k][tx * TN + j];
                b[j] = bv.x; b[j + 1] = bv.y; b[j + 2] = bv.z; b[j + 3] = bv.w;
            }
#pragma unroll
            for (int i = 0; i < TM; i++)
#pragma unroll
                for (int j = 0; j < TN; j++)
                    acc[i][j] += aa[i] * b[j];
        }
        __syncthreads();
    }

    // epilogue: bias add + store
#pragma unroll
    for (int i = 0; i < TM; i++) {
        int r = row0 + ty * TM + i;
        if (r < NN) {
#pragma unroll
            for (int j = 0; j < TN; j += 4) {
                int c = tx * TN + j;
                float4 o;
                o.x = acc[i][j + 0] + bias[c + 0];
                o.y = acc[i][j + 1] + bias[c + 1];
                o.z = acc[i][j + 2] + bias[c + 2];
                o.w = acc[i][j + 3] + bias[c + 3];
                *(float4*)&C[(size_t)r * BN + c] = o;
            }
        }
    }
}

// ---------------- gather-sum (replaces scatter-add): out[i] = sum_{e in CSR(i)} m[src_e] ----------------
// one warp per node, float4 per lane (32 lanes x 4 = 128 cols)
__global__ void gather_kernel(const float* __restrict__ m, float* __restrict__ out) {
    int gw = (blockIdx.x * blockDim.x + threadIdx.x) >> 5;
    int lane = threadIdx.x & 31;
    if (gw >= NN) return;
    int beg = g_off[gw];
    int end = g_off[gw + 1];
    float4 acc = make_float4(0.f, 0.f, 0.f, 0.f);
    for (int e = beg; e < end; e++) {
        int s = g_csr[e];
        float4 v = *(const float4*)&m[(size_t)s * DD + lane * 4];
        acc.x += v.x; acc.y += v.y; acc.z += v.z; acc.w += v.w;
    }
    *(float4*)&out[(size_t)gw * DD + lane * 4] = acc;
}

// ---------------- launch ----------------
extern "C" void kernel_launch(void* const* d_in, const int* in_sizes, int n_in,
                              void* d_out, int out_size) {
    const float* x    = (const float*)d_in[0];
    const void*  ei   = d_in[1];
    const float* W1   = (const float*)d_in[2];
    const float* b1   = (const float*)d_in[3];
    const float* W2   = (const float*)d_in[4];
    const float* b2   = (const float*)d_in[5];
    const float* Wout = (const float*)d_in[6];
    const float* bout = (const float*)d_in[7];
    float* out = (float*)d_out;

    float *bufA = nullptr, *bufB = nullptr;
    cudaGetSymbolAddress((void**)&bufA, g_bufA);
    cudaGetSymbolAddress((void**)&bufB, g_bufB);

    // CSR build (once per launch; replayed in graph)
    detect_kernel<<<1, 1>>>((const unsigned int*)ei);
    zero_kernel<<<(NN + 255) / 256, 256>>>();
    hist_kernel<<<(EE + 255) / 256, 256>>>(ei);
    scan_kernel<<<1, 1024>>>();
    fill_kernel<<<(EE + 255) / 256, 256>>>(ei);

    const int gb = (NN + 63) / 64;              // 782 blocks
    const int gg = (NN * 32 + 255) / 256;       // 6250 blocks (warp per node)

    // pool layer 1 (W1) x2
    gemm_kernel<128, 8><<<gb, 256>>>(x,    W1, b1, bufA, 0);
    gather_kernel<<<gg, 256>>>(bufA, bufB);
    gemm_kernel<128, 8><<<gb, 256>>>(bufB, W1, b1, bufA, 0);
    gather_kernel<<<gg, 256>>>(bufA, bufB);
    // relu fused into next gemm's A-load
    // pool layer 2 (W2) x2
    gemm_kernel<128, 8><<<gb, 256>>>(bufB, W2, b2, bufA, 1);
    gather_kernel<<<gg, 256>>>(bufA, bufB);
    gemm_kernel<128, 8><<<gb, 256>>>(bufB, W2, b2, bufA, 0);
    gather_kernel<<<gg, 256>>>(bufA, bufB);
    // output projection with fused relu
    gemm_kernel<64, 4><<<gb, 256>>>(bufB, Wout, bout, out, 1);
}

// round 3
// speedup vs baseline: 1.8055x; 1.8055x over previous
#include <cuda_runtime.h>
#include <cuda_bf16.h>
#include <cstdint>

#define NN   50000
#define EE   600000
#define DD   128
#define DOUT 64
#define NB   ((NN + 255) / 256)   // 196 blocks for scans

// ---------------- scratch (no allocation allowed) ----------------
__device__ float          g_m[(size_t)NN * DD];        // gemm output (fp32)
__device__ __nv_bfloat16  g_hA[(size_t)NN * DD];       // split-hi activations
__device__ __nv_bfloat16  g_lA[(size_t)NN * DD];       // split-lo activations
__device__ __nv_bfloat16  g_w1h[DD * DD], g_w1l[DD * DD];
__device__ __nv_bfloat16  g_w2h[DD * DD], g_w2l[DD * DD];
__device__ __nv_bfloat16  g_woh[DOUT * DD], g_wol[DOUT * DD];
__device__ int   g_deg[NN];
__device__ int   g_cnt[NN];
__device__ int   g_off[NN + 1];
__device__ int   g_part[NB];
__device__ int   g_poff[NB];
__device__ int   g_csr[EE];
__device__ int   g_is64;

__device__ __forceinline__ uint32_t smem_u32(const void* p) {
    uint32_t a;
    asm("{ .reg .u64 t; cvta.to.shared.u64 t, %1; cvt.u32.u64 %0, t; }" : "=r"(a) : "l"(p));
    return a;
}

// ---------------- edge_index dtype sniffing ----------------
__global__ void detect_kernel(const unsigned int* __restrict__ w) {
    int is64 = 1;
    for (int i = 1; i < 128; i += 2)
        if (w[i] != 0u) { is64 = 0; break; }
    g_is64 = is64;
}
__device__ __forceinline__ int edge_idx(const void* ei, int which, int e) {
    if (g_is64) return (int)((const long long*)ei)[(size_t)which * EE + e];
    return ((const int*)ei)[which * EE + e];
}

// ---------------- CSR build ----------------
__global__ void zero_kernel() {
    int i = blockIdx.x * blockDim.x + threadIdx.x;
    if (i < NN) { g_deg[i] = 0; g_cnt[i] = 0; }
}
__global__ void hist_kernel(const void* ei) {
    int e = blockIdx.x * blockDim.x + threadIdx.x;
    if (e < EE) atomicAdd(&g_deg[edge_idx(ei, 1, e)], 1);
}
__global__ void partial_kernel() {
    __shared__ int sh[256];
    int t = threadIdx.x, i = blockIdx.x * 256 + t;
    sh[t] = (i < NN) ? g_deg[i] : 0;
    __syncthreads();
    for (int d = 128; d > 0; d >>= 1) {
        if (t < d) sh[t] += sh[t + d];
        __syncthreads();
    }
    if (t == 0) g_part[blockIdx.x] = sh[0];
}
__global__ void scanpart_kernel() {
    __shared__ int sh[256];
    int t = threadIdx.x;
    int v = (t < NB) ? g_part[t] : 0;
    sh[t] = v;
    __syncthreads();
    for (int d = 1; d < 256; d <<= 1) {
        int u = (t >= d) ? sh[t - d] : 0;
        __syncthreads();
        sh[t] += u;
        __syncthreads();
    }
    if (t < NB) g_poff[t] = sh[t] - v;   // exclusive
    if (t == 0) g_off[NN] = EE;
}
__global__ void offs_kernel() {
    __shared__ int sh[256];
    int t = threadIdx.x, i = blockIdx.x * 256 + t;
    int v = (i < NN) ? g_deg[i] : 0;
    sh[t] = v;
    __syncthreads();
    for (int d = 1; d < 256; d <<= 1) {
        int u = (t >= d) ? sh[t - d] : 0;
        __syncthreads();
        sh[t] += u;
        __syncthreads();
    }
    if (i < NN) g_off[i] = g_poff[blockIdx.x] + sh[t] - v;
}
__global__ void fill_kernel(const void* ei) {
    int e = blockIdx.x * blockDim.x + threadIdx.x;
    if (e < EE) {
        int d = edge_idx(ei, 1, e);
        int s = edge_idx(ei, 0, e);
        g_csr[g_off[d] + atomicAdd(&g_cnt[d], 1)] = s;
    }
}

// ---------------- fp32 -> (hi, lo) bf16 split ----------------
__device__ __forceinline__ void split2(float x, __nv_bfloat16& h, __nv_bfloat16& l) {
    h = __float2bfloat16(x);
    l = __float2bfloat16(x - __bfloat162float(h));
}

__global__ void convert_x_kernel(const float* __restrict__ x) {
    int i = blockIdx.x * blockDim.x + threadIdx.x;   // per float4
    if (i >= NN * DD / 4) return;
    float4 v = ((const float4*)x)[i];
    __nv_bfloat16 h[4], l[4];
    split2(v.x, h[0], l[0]); split2(v.y, h[1], l[1]);
    split2(v.z, h[2], l[2]); split2(v.w, h[3], l[3]);
    ((uint2*)g_hA)[i] = *(uint2*)h;
    ((uint2*)g_lA)[i] = *(uint2*)l;
}

// transpose + split W[K,N] -> Wt[N,K]
__global__ void tw_kernel(const float* __restrict__ W, __nv_bfloat16* __restrict__ hi,
                          __nv_bfloat16* __restrict__ lo, int Ncols) {
    int o = blockIdx.x * blockDim.x + threadIdx.x;   // o = n*128 + k
    if (o >= Ncols * DD) return;
    int n = o >> 7, k = o & 127;
    split2(W[k * Ncols + n], hi[o], lo[o]);
}

// ---------------- HMMA split-bf16 GEMM ----------------
// C[128 rows per CTA, N] = (hA+lA)[.,128] @ (Bh+Bl)^T + bias
// 3 K-passes (Ahi*Bhi, Ahi*Blo, Alo*Bhi), fp32 accumulate in mma.sync.
// smem XOR-swizzled row-major tiles (row stride 256B, 16B chunk ^= row&7).
template <int N>
__global__ void __launch_bounds__(256) gemm_mma(
    const __nv_bfloat16* __restrict__ Ahi, const __nv_bfloat16* __restrict__ Alo,
    const __nv_bfloat16* __restrict__ Bhi, const __nv_bfloat16* __restrict__ Blo,
    const float* __restrict__ bias, float* __restrict__ C)
{
    extern __shared__ char smem[];
    constexpr int AHI = 0, ALO = 32768, BHIOFF = 65536, BLOOFF = 65536 + N * 256;
    constexpr int NW = N / 2;       // warp n-tile (64 / 32)
    constexpr int NF16 = NW / 16;   // 4 / 2
    constexpr int NF8 = NW / 8;     // 8 / 4

    uint32_t sb = smem_u32(smem);
    int tid = threadIdx.x, wid = tid >> 5, lane = tid & 31;
    int row0 = blockIdx.x * 128;

    // stage A hi+lo (128 rows x 16 chunks of 16B)
    for (int idx = tid; idx < 2048; idx += 256) {
        int r = idx >> 4, ch = idx & 15;
        int grow = row0 + r;
        uint4 vh = make_uint4(0, 0, 0, 0), vl = vh;
        if (grow < NN) {
            vh = *(const uint4*)(Ahi + (size_t)grow * DD + ch * 8);
            vl = *(const uint4*)(Alo + (size_t)grow * DD + ch * 8);
        }
        int off = r * 256 + ((ch ^ (r & 7)) << 4);
        *(uint4*)(smem + AHI + off) = vh;
        *(uint4*)(smem + ALO + off) = vl;
    }
    // stage B hi+lo (N rows x 16 chunks)
    for (int idx = tid; idx < N * 16; idx += 256) {
        int r = idx >> 4, ch = idx & 15;
        uint4 vh = *(const uint4*)(Bhi + r * DD + ch * 8);
        uint4 vl = *(const uint4*)(Blo + r * DD + ch * 8);
        int off = r * 256 + ((ch ^ (r & 7)) << 4);
        *(uint4*)(smem + BHIOFF + off) = vh;
        *(uint4*)(smem + BLOOFF + off) = vl;
    }
    __syncthreads();

    int wr = wid & 3, wc = wid >> 2;
    int lr = lane & 7;
    // A ldmatrix lane mapping: x4 = (rows0-7,c0)(rows8-15,c0)(rows0-7,c0+1)(rows8-15,c0+1)
    int a_half = (lane >> 3) & 1, a_kc = lane >> 4;
    uint32_t a_rb[2];
#pragma unroll
    for (int mf = 0; mf < 2; mf++)
        a_rb[mf] = (uint32_t)((wr * 32 + mf * 16 + a_half * 8 + lr) * 256);
    // B ldmatrix lane mapping: x4 = (nlo,c0)(nlo,c0+1)(nhi,c0)(nhi,c0+1)
    int b_kc = (lane >> 3) & 1, b_nh = lane >> 4;
    uint32_t b_rb[NF16];
#pragma unroll
    for (int nf = 0; nf < NF16; nf++)
        b_rb[nf] = (uint32_t)((wc * NW + nf * 16 + b_nh * 8 + lr) * 256);

    float acc[2][NF8][4];
#pragma unroll
    for (int mf = 0; mf < 2; mf++)
#pragma unroll
        for (int n8 = 0; n8 < NF8; n8++)
#pragma unroll
            for (int j = 0; j < 4; j++) acc[mf][n8][j] = 0.f;

    for (int ks = 0; ks < 24; ks++) {
        int s = ks >> 3;
        int c0 = (ks & 7) * 2;
        uint32_t Ab = sb + (s == 2 ? ALO : AHI);
        uint32_t Bb = sb + (s == 1 ? BLOOFF : BHIOFF);

        uint32_t a[2][4];
#pragma unroll
        for (int mf = 0; mf < 2; mf++) {
            uint32_t addr = Ab + a_rb[mf] + (uint32_t)(((c0 + a_kc) ^ lr) << 4);
            asm volatile("ldmatrix.sync.aligned.m8n8.x4.shared.b16 {%0,%1,%2,%3}, [%4];"
                : "=r"(a[mf][0]), "=r"(a[mf][1]), "=r"(a[mf][2]), "=r"(a[mf][3]) : "r"(addr));
        }
#pragma unroll
        for (int nf = 0; nf < NF16; nf++) {
            uint32_t addr = Bb + b_rb[nf] + (uint32_t)(((c0 + b_kc) ^ lr) << 4);
            uint32_t b0, b1, b2, b3;
            asm volatile("ldmatrix.sync.aligned.m8n8.x4.shared.b16 {%0,%1,%2,%3}, [%4];"
                : "=r"(b0), "=r"(b1), "=r"(b2), "=r"(b3) : "r"(addr));
#pragma unroll
            for (int mf = 0; mf < 2; mf++) {
                float* c = acc[mf][2 * nf];
                asm volatile("mma.sync.aligned.m16n8k16.row.col.f32.bf16.bf16.f32 "
                    "{%0,%1,%2,%3}, {%4,%5,%6,%7}, {%8,%9}, {%0,%1,%2,%3};"
                    : "+f"(c[0]), "+f"(c[1]), "+f"(c[2]), "+f"(c[3])
                    : "r"(a[mf][0]), "r"(a[mf][1]), "r"(a[mf][2]), "r"(a[mf][3]),
                      "r"(b0), "r"(b1));
                float* d = acc[mf][2 * nf + 1];
                asm volatile("mma.sync.aligned.m16n8k16.row.col.f32.bf16.bf16.f32 "
                    "{%0,%1,%2,%3}, {%4,%5,%6,%7}, {%8,%9}, {%0,%1,%2,%3};"
                    : "+f"(d[0]), "+f"(d[1]), "+f"(d[2]), "+f"(d[3])
                    : "r"(a[mf][0]), "r"(a[mf][1]), "r"(a[mf][2]), "r"(a[mf][3]),
                      "r"(b2), "r"(b3));
            }
        }
    }

    // epilogue
    int g = lane >> 2, tg = lane & 3;
#pragma unroll
    for (int mf = 0; mf < 2; mf++) {
        int r = row0 + wr * 32 + mf * 16 + g;
#pragma unroll
        for (int n8 = 0; n8 < NF8; n8++) {
            int c = wc * NW + n8 * 8 + tg * 2;
            float bx = bias[c], by = bias[c + 1];
            float* a0 = acc[mf][n8];
            if (r < NN)
                *(float2*)(C + (size_t)r * N + c) = make_float2(a0[0] + bx, a0[1] + by);
            if (r + 8 < NN)
                *(float2*)(C + (size_t)(r + 8) * N + c) = make_float2(a0[2] + bx, a0[3] + by);
        }
    }
}

// ---------------- gather-sum with fused relu + bf16 split output ----------------
__global__ void gather_kernel(const float* __restrict__ m, int relu) {
    int gw = (blockIdx.x * blockDim.x + threadIdx.x) >> 5;
    int lane = threadIdx.x & 31;
    if (gw >= NN) return;
    int beg = g_off[gw], end = g_off[gw + 1];
    float4 acc = make_float4(0.f, 0.f, 0.f, 0.f);
    for (int e = beg; e < end; e++) {
        int s = g_csr[e];
        float4 v = *(const float4*)&m[(size_t)s * DD + lane * 4];
        acc.x += v.x; acc.y += v.y; acc.z += v.z; acc.w += v.w;
    }
    if (relu) {
        acc.x = fmaxf(acc.x, 0.f); acc.y = fmaxf(acc.y, 0.f);
        acc.z = fmaxf(acc.z, 0.f); acc.w = fmaxf(acc.w, 0.f);
    }
    __nv_bfloat16 h[4], l[4];
    split2(acc.x, h[0], l[0]); split2(acc.y, h[1], l[1]);
    split2(acc.z, h[2], l[2]); split2(acc.w, h[3], l[3]);
    size_t o = ((size_t)gw * DD + lane * 4) >> 2;
    ((uint2*)g_hA)[o] = *(uint2*)h;
    ((uint2*)g_lA)[o] = *(uint2*)l;
}

// ---------------- launch ----------------
extern "C" void kernel_launch(void* const* d_in, const int* in_sizes, int n_in,
                              void* d_out, int out_size) {
    const float* x    = (const float*)d_in[0];
    const void*  ei   = d_in[1];
    const float* W1   = (const float*)d_in[2];
    const float* b1   = (const float*)d_in[3];
    const float* W2   = (const float*)d_in[4];
    const float* b2   = (const float*)d_in[5];
    const float* Wout = (const float*)d_in[6];
    const float* bout = (const float*)d_in[7];
    float* out = (float*)d_out;

    float* m;  __nv_bfloat16 *hA, *lA, *w1h, *w1l, *w2h, *w2l, *woh, *wol;
    cudaGetSymbolAddress((void**)&m,   g_m);
    cudaGetSymbolAddress((void**)&hA,  g_hA);
    cudaGetSymbolAddress((void**)&lA,  g_lA);
    cudaGetSymbolAddress((void**)&w1h, g_w1h); cudaGetSymbolAddress((void**)&w1l, g_w1l);
    cudaGetSymbolAddress((void**)&w2h, g_w2h); cudaGetSymbolAddress((void**)&w2l, g_w2l);
    cudaGetSymbolAddress((void**)&woh, g_woh); cudaGetSymbolAddress((void**)&wol, g_wol);

    const int SM128 = 65536 + 128 * 512;   // 131072
    const int SM64  = 65536 + 64 * 512;    // 98304
    static bool attr_done = false;
    if (!attr_done) {
        cudaFuncSetAttribute(gemm_mma<128>, cudaFuncAttributeMaxDynamicSharedMemorySize, SM128);
        cudaFuncSetAttribute(gemm_mma<64>,  cudaFuncAttributeMaxDynamicSharedMemorySize, SM64);
        attr_done = true;
    }

    // CSR build
    detect_kernel<<<1, 1>>>((const unsigned int*)ei);
    zero_kernel<<<NB, 256>>>();
    hist_kernel<<<(EE + 255) / 256, 256>>>(ei);
    partial_kernel<<<NB, 256>>>();
    scanpart_kernel<<<1, 256>>>();
    offs_kernel<<<NB, 256>>>();
    fill_kernel<<<(EE + 255) / 256, 256>>>(ei);

    // weight + input prep
    tw_kernel<<<(DD * DD + 255) / 256, 256>>>(W1, w1h, w1l, DD);
    tw_kernel<<<(DD * DD + 255) / 256, 256>>>(W2, w2h, w2l, DD);
    tw_kernel<<<(DOUT * DD + 255) / 256, 256>>>(Wout, woh, wol, DOUT);
    convert_x_kernel<<<(NN * DD / 4 + 255) / 256, 256>>>(x);

    const int gb = (NN + 127) / 128;        // 391 CTAs
    const int gg = (NN * 32 + 255) / 256;   // warp per node

    gemm_mma<128><<<gb, 256, SM128>>>(hA, lA, w1h, w1l, b1, m);
    gather_kernel<<<gg, 256>>>(m, 0);
    gemm_mma<128><<<gb, 256, SM128>>>(hA, lA, w1h, w1l, b1, m);
    gather_kernel<<<gg, 256>>>(m, 1);       // relu after pool 1
    gemm_mma<128><<<gb, 256, SM128>>>(hA, lA, w2h, w2l, b2, m);
    gather_kernel<<<gg, 256>>>(m, 0);
    gemm_mma<128><<<gb, 256, SM128>>>(hA, lA, w2h, w2l, b2, m);
    gather_kernel<<<gg, 256>>>(m, 1);       // relu after pool 2
    gemm_mma<64><<<gb, 256, SM64>>>(hA, lA, woh, wol, bout, out);
}